// round 3
// baseline (speedup 1.0000x reference)
#include <cuda_runtime.h>
#include <math_constants.h>

// Problem constants (fixed by the reference): B=8, N=M=4096, 3-D points.
constexpr int BATCH = 8;
constexpr int NPTS  = 4096;

constexpr int SPLITS         = 16;                 // M split across blocks
constexpr int COLS_PER_SPLIT = NPTS / SPLITS;      // 256
constexpr int THREADS        = 256;
constexpr int P2             = 4;                  // packed row-PAIRS per thread (8 rows)
constexpr int ROWS_PER_BLOCK = THREADS * P2 * 2;   // 2048
constexpr int ROW_TILES      = NPTS / ROWS_PER_BLOCK; // 2
constexpr int RBLOCKS        = 64;

// Partial row-mins, layout [dir][b][row][split]: 2*8*4096*16 floats = 4 MB.
__device__ float  g_partial[2 * BATCH * NPTS * SPLITS];
__device__ double g_acc[3];   // [0]=chamfer, [1]=emd sqrt sum, [2]=uncertainty sum

__global__ void init_kernel() {
    g_acc[0] = 0.0; g_acc[1] = 0.0; g_acc[2] = 0.0;
}

// ---- packed f32x2 helpers (sm_100+: fma.rn.f32x2 -> FFMA2 in SASS) ----
__device__ __forceinline__ unsigned long long pack2(float lo, float hi) {
    unsigned long long r;
    asm("mov.b64 %0, {%1, %2};" : "=l"(r) : "f"(lo), "f"(hi));
    return r;
}
__device__ __forceinline__ float2 unpack2(unsigned long long v) {
    float2 f;
    asm("mov.b64 {%0, %1}, %2;" : "=f"(f.x), "=f"(f.y) : "l"(v));
    return f;
}
__device__ __forceinline__ unsigned long long fma2(
    unsigned long long a, unsigned long long b, unsigned long long c) {
    unsigned long long d;
    asm("fma.rn.f32x2 %0, %1, %2, %3;" : "=l"(d) : "l"(a), "l"(b), "l"(c));
    return d;
}

// For each row point p and column tile: min over cols of
//   d2 = ||p||^2 + ||t||^2 - 2 p.t
// Columns pre-transformed to (-2x,-2y,-2z,||t||^2), DUPLICATED into f32x2 lanes
// so two rows are processed per FFMA2. ||p||^2 is added once at the end.
__global__ __launch_bounds__(THREADS) void pair_min_kernel(
    const float* __restrict__ pred, const float* __restrict__ tgt)
{
    const int dir = blockIdx.z & 1;        // 0: rows=pred, cols=target; 1: swapped
    const int b   = blockIdx.z >> 1;
    const float* __restrict__ rows = dir ? tgt  : pred;
    const float* __restrict__ cols = dir ? pred : tgt;

    // Duplicated column data: scA[c] = { {-2x,-2x}, {-2y,-2y} },
    //                         scB[c] = { {-2z,-2z}, { w , w } }.  8 KB total.
    __shared__ ulonglong2 scA[COLS_PER_SPLIT];
    __shared__ ulonglong2 scB[COLS_PER_SPLIT];

    const int c0 = blockIdx.y * COLS_PER_SPLIT;
    for (int j = threadIdx.x; j < COLS_PER_SPLIT; j += THREADS) {
        const float* cp = cols + ((size_t)b * NPTS + c0 + j) * 3;
        float x = cp[0], y = cp[1], z = cp[2];
        float w = x * x + y * y + z * z;
        scA[j] = make_ulonglong2(pack2(-2.0f * x, -2.0f * x),
                                 pack2(-2.0f * y, -2.0f * y));
        scB[j] = make_ulonglong2(pack2(-2.0f * z, -2.0f * z),
                                 pack2(w, w));
    }
    __syncthreads();

    // Each thread owns 8 rows as 4 packed pairs: rows rbase + (2j)*THREADS (lo)
    // and rbase + (2j+1)*THREADS (hi).
    unsigned long long px2[P2], py2[P2], pz2[P2];
    float mnlo[P2], mnhi[P2];
    const int rbase = blockIdx.x * ROWS_PER_BLOCK + threadIdx.x;
#pragma unroll
    for (int j = 0; j < P2; ++j) {
        const float* r0 = rows + ((size_t)b * NPTS + rbase + (2 * j)     * THREADS) * 3;
        const float* r1 = rows + ((size_t)b * NPTS + rbase + (2 * j + 1) * THREADS) * 3;
        px2[j] = pack2(r0[0], r1[0]);
        py2[j] = pack2(r0[1], r1[1]);
        pz2[j] = pack2(r0[2], r1[2]);
        mnlo[j] = CUDART_INF_F;
        mnhi[j] = CUDART_INF_F;
    }

#pragma unroll 4
    for (int c = 0; c < COLS_PER_SPLIT; ++c) {
        const ulonglong2 ta = scA[c];   // { -2x dup, -2y dup }
        const ulonglong2 tb = scB[c];   // { -2z dup,   w dup }
#pragma unroll
        for (int j = 0; j < P2; ++j) {
            unsigned long long v = fma2(pz2[j], tb.x, tb.y);
            v = fma2(py2[j], ta.y, v);
            v = fma2(px2[j], ta.x, v);
            float2 vf = unpack2(v);     // register aliasing, no SASS cost
            mnlo[j] = fminf(mnlo[j], vf.x);
            mnhi[j] = fminf(mnhi[j], vf.y);
        }
    }

    const int split = blockIdx.y;
#pragma unroll
    for (int j = 0; j < P2; ++j) {
        float2 x = unpack2(px2[j]), y = unpack2(py2[j]), z = unpack2(pz2[j]);
        const int r0 = rbase + (2 * j) * THREADS;
        const int r1 = rbase + (2 * j + 1) * THREADS;
        float psq0 = fmaf(x.x, x.x, fmaf(y.x, y.x, z.x * z.x));
        float psq1 = fmaf(x.y, x.y, fmaf(y.y, y.y, z.y * z.y));
        const size_t base = ((size_t)dir * BATCH + b) * NPTS;
        g_partial[(base + r0) * SPLITS + split] = psq0 + mnlo[j];
        g_partial[(base + r1) * SPLITS + split] = psq1 + mnhi[j];
    }
}

__global__ __launch_bounds__(256) void reduce_kernel(const float* __restrict__ unc) {
    double cham = 0.0, emd = 0.0, us = 0.0;

    const int total_rows = 2 * BATCH * NPTS;   // 65536
    for (int i = blockIdx.x * 256 + threadIdx.x; i < total_rows; i += RBLOCKS * 256) {
        const float4* p = reinterpret_cast<const float4*>(&g_partial[(size_t)i * SPLITS]);
        float m = CUDART_INF_F;
#pragma unroll
        for (int k = 0; k < SPLITS / 4; ++k) {
            float4 a = p[k];
            m = fminf(m, fminf(fminf(a.x, a.y), fminf(a.z, a.w)));
        }
        cham += (double)m;
        if (i < BATCH * NPTS)                     // dir-0 (pred) rows only
            emd += (double)sqrtf(fmaxf(m, 0.0f)); // reference clips d2 before sqrt
    }
    for (int i = blockIdx.x * 256 + threadIdx.x; i < BATCH * NPTS; i += RBLOCKS * 256)
        us += (double)unc[i];

    __shared__ double sc_[256], se_[256], su_[256];
    sc_[threadIdx.x] = cham; se_[threadIdx.x] = emd; su_[threadIdx.x] = us;
    __syncthreads();
    for (int s = 128; s > 0; s >>= 1) {
        if (threadIdx.x < s) {
            sc_[threadIdx.x] += sc_[threadIdx.x + s];
            se_[threadIdx.x] += se_[threadIdx.x + s];
            su_[threadIdx.x] += su_[threadIdx.x + s];
        }
        __syncthreads();
    }
    if (threadIdx.x == 0) {
        atomicAdd(&g_acc[0], sc_[0]);
        atomicAdd(&g_acc[1], se_[0]);
        atomicAdd(&g_acc[2], su_[0]);
    }
}

__global__ void final_kernel(float* out) {
    const double inv = 1.0 / (double)(BATCH * NPTS);
    // total = chamfer*1.0 + emd*0.5 + mean(uncertainty)*0.01
    out[0] = (float)(g_acc[0] * inv + 0.5 * (g_acc[1] * inv) + 0.01 * (g_acc[2] * inv));
}

extern "C" void kernel_launch(void* const* d_in, const int* in_sizes, int n_in,
                              void* d_out, int out_size) {
    const float* pred = (const float*)d_in[0];   // [B, N, 3]
    const float* tgt  = (const float*)d_in[1];   // [B, M, 3]
    const float* unc  = (const float*)d_in[2];   // [B, N]
    float* out = (float*)d_out;                  // scalar

    init_kernel<<<1, 1>>>();
    dim3 grid(ROW_TILES, SPLITS, 2 * BATCH);     // 2 x 16 x 16 = 512 blocks
    pair_min_kernel<<<grid, THREADS>>>(pred, tgt);
    reduce_kernel<<<RBLOCKS, 256>>>(unc);
    final_kernel<<<1, 1>>>(out);
}

// round 14
// speedup vs baseline: 1.2335x; 1.2335x over previous
#include <cuda_runtime.h>
#include <math_constants.h>

// Problem constants (fixed by the reference): B=8, N=M=4096, 3-D points.
constexpr int BATCH = 8;
constexpr int NPTS  = 4096;

constexpr int THREADS        = 256;
constexpr int P2             = 4;                    // packed row-pairs / thread (8 rows)
constexpr int ROWS_PER_BLOCK = THREADS * P2 * 2;     // 2048
constexpr int ROW_TILES      = NPTS / ROWS_PER_BLOCK;   // 2
constexpr int COLS_PER_BLOCK = 256;
constexpr int COL_TILES      = NPTS / COLS_PER_BLOCK;   // 16
constexpr int NCHUNK         = COLS_PER_BLOCK / 32;     // 8
constexpr int RBLOCKS        = 64;

// Row-min partials [b][row][col_tile] (2 MB) and col-min partials [b][col][row_tile].
__device__ float g_rowpart[BATCH * NPTS * COL_TILES];
__device__ float g_colpart[BATCH * NPTS * ROW_TILES];
__device__ double g_bsum[RBLOCKS][3];     // per-reduce-block partials: cham, emd, unc
__device__ unsigned int g_count = 0;      // election counter (reset by elected block)

// ---- packed f32x2 helpers (sm_100+) ----
__device__ __forceinline__ unsigned long long pack2(float lo, float hi) {
    unsigned long long r;
    asm("mov.b64 %0, {%1, %2};" : "=l"(r) : "f"(lo), "f"(hi));
    return r;
}
__device__ __forceinline__ float2 unpack2(unsigned long long v) {
    float2 f;
    asm("mov.b64 {%0, %1}, %2;" : "=f"(f.x), "=f"(f.y) : "l"(v));
    return f;
}
__device__ __forceinline__ unsigned long long fma2(
    unsigned long long a, unsigned long long b, unsigned long long c) {
    unsigned long long d;
    asm("fma.rn.f32x2 %0, %1, %2, %3;" : "=l"(d) : "l"(a), "l"(b), "l"(c));
    return d;
}
__device__ __forceinline__ unsigned long long add2(
    unsigned long long a, unsigned long long b) {
    unsigned long long d;
    asm("add.rn.f32x2 %0, %1, %2;" : "=l"(d) : "l"(a), "l"(b));
    return d;
}

// Single pass over the d2 matrix tile: rows = pred (2048/block), cols = target
// (256/block). Produces BOTH row-mins (pred->tgt) and col-mins (tgt->pred).
//   v' = psq - 2 p.t   (FFMA2 chain seeded with psq; col-min folds this, tsq
//                       is per-column constant added at store time)
//   d2 = v' + tsq      (row-min folds the full value)
// Col-min across lanes: skewed column assignment (lane+s) with a SHFL-rotated
// accumulator. Token invariant: a token born at lane k sits at lane k-s at
// step s and reads column (lane+s)&31 = k; after 32 steps it has visited all
// 32 lanes' rows and is back at lane k.
__global__ __launch_bounds__(THREADS) void pair_min_kernel(
    const float* __restrict__ pred, const float* __restrict__ tgt)
{
    const int rowtile = blockIdx.x;
    const int coltile = blockIdx.y;
    const int b       = blockIdx.z;

    // Column data duplicated twice per 32-col chunk (entries [c, c+32] equal)
    // so skewed access A[lane + s] needs no wrap mask.
    __shared__ ulonglong2 scA[2 * COLS_PER_BLOCK];  // { {-2x,-2x}, {-2y,-2y} }
    __shared__ ulonglong2 scB[2 * COLS_PER_BLOCK];  // { {-2z,-2z}, {tsq,tsq} }
    __shared__ float      sw[COLS_PER_BLOCK];       // tsq
    __shared__ float      colwmin[8][COLS_PER_BLOCK];

    {
        const int j = threadIdx.x;                  // 256 threads, 256 cols
        const float* cp = tgt + ((size_t)b * NPTS + coltile * COLS_PER_BLOCK + j) * 3;
        float x = cp[0], y = cp[1], z = cp[2];
        float w = x * x + y * y + z * z;
        ulonglong2 a  = make_ulonglong2(pack2(-2.0f * x, -2.0f * x),
                                        pack2(-2.0f * y, -2.0f * y));
        ulonglong2 bb = make_ulonglong2(pack2(-2.0f * z, -2.0f * z),
                                        pack2(w, w));
        const int base = (j >> 5) * 64 + (j & 31);
        scA[base] = a;  scA[base + 32] = a;
        scB[base] = bb; scB[base + 32] = bb;
        sw[j] = w;
    }

    // Per-thread rows: rbase + k*THREADS for k=0..7, packed as 4 f32x2 pairs.
    unsigned long long px2[P2], py2[P2], pz2[P2], psq2[P2];
    float mnlo[P2], mnhi[P2];
    const int rbase = rowtile * ROWS_PER_BLOCK + threadIdx.x;
#pragma unroll
    for (int j = 0; j < P2; ++j) {
        const float* r0 = pred + ((size_t)b * NPTS + rbase + (2 * j)     * THREADS) * 3;
        const float* r1 = pred + ((size_t)b * NPTS + rbase + (2 * j + 1) * THREADS) * 3;
        float x0 = r0[0], y0 = r0[1], z0 = r0[2];
        float x1 = r1[0], y1 = r1[1], z1 = r1[2];
        px2[j] = pack2(x0, x1);
        py2[j] = pack2(y0, y1);
        pz2[j] = pack2(z0, z1);
        psq2[j] = pack2(fmaf(x0, x0, fmaf(y0, y0, z0 * z0)),
                        fmaf(x1, x1, fmaf(y1, y1, z1 * z1)));
        mnlo[j] = CUDART_INF_F;
        mnhi[j] = CUDART_INF_F;
    }
    __syncthreads();

    const int lane = threadIdx.x & 31;
    const int wid  = threadIdx.x >> 5;
    const int nxt  = (lane + 1) & 31;

    for (int chunk = 0; chunk < NCHUNK; ++chunk) {
        const ulonglong2* A  = scA + chunk * 64;
        const ulonglong2* Bc = scB + chunk * 64;
        float acc = CUDART_INF_F;
#pragma unroll 8
        for (int s = 0; s < 32; ++s) {
            const ulonglong2 ta = A[lane + s];
            const ulonglong2 tb = Bc[lane + s];
            float2 vc[P2];
#pragma unroll
            for (int j = 0; j < P2; ++j) {
                unsigned long long v = fma2(pz2[j], tb.x, psq2[j]);
                v = fma2(py2[j], ta.y, v);
                v = fma2(px2[j], ta.x, v);        // v = psq - 2 p.t
                float2 vr = unpack2(add2(v, tb.y)); // + tsq -> full d2
                mnlo[j] = fminf(mnlo[j], vr.x);
                mnhi[j] = fminf(mnhi[j], vr.y);
                vc[j] = unpack2(v);
            }
            // tree-fold step-local col contribution, then one dependent min
            float m01 = fminf(fminf(vc[0].x, vc[0].y), fminf(vc[1].x, vc[1].y));
            float m23 = fminf(fminf(vc[2].x, vc[2].y), fminf(vc[3].x, vc[3].y));
            acc = fminf(acc, fminf(m01, m23));
            acc = __shfl_sync(0xffffffffu, acc, nxt);   // rotate accumulators down
        }
        colwmin[wid][chunk * 32 + lane] = acc;  // warp's 256-row min for this col
    }
    __syncthreads();

    // Row-min partials (full d2 already).
#pragma unroll
    for (int j = 0; j < P2; ++j) {
        const int r0 = rbase + (2 * j) * THREADS;
        const int r1 = rbase + (2 * j + 1) * THREADS;
        g_rowpart[((size_t)b * NPTS + r0) * COL_TILES + coltile] = mnlo[j];
        g_rowpart[((size_t)b * NPTS + r1) * COL_TILES + coltile] = mnhi[j];
    }
    // Col-min partials: fold 8 warps, add back tsq.
    {
        const int c = threadIdx.x;
        float m = colwmin[0][c];
#pragma unroll
        for (int w = 1; w < 8; ++w) m = fminf(m, colwmin[w][c]);
        m += sw[c];
        const int gcol = coltile * COLS_PER_BLOCK + c;
        g_colpart[((size_t)b * NPTS + gcol) * ROW_TILES + rowtile] = m;
    }
}

__global__ __launch_bounds__(256) void reduce_kernel(const float* __restrict__ unc,
                                                     float* __restrict__ out) {
    double cham = 0.0, emd = 0.0, us = 0.0;
    const int tid = blockIdx.x * 256 + threadIdx.x;

    // pred-side row mins: min over 16 col-tiles; chamfer + emd(sqrt).
    for (int i = tid; i < BATCH * NPTS; i += RBLOCKS * 256) {
        const float4* p = reinterpret_cast<const float4*>(&g_rowpart[(size_t)i * COL_TILES]);
        float m = CUDART_INF_F;
#pragma unroll
        for (int k = 0; k < COL_TILES / 4; ++k) {
            float4 a = p[k];
            m = fminf(m, fminf(fminf(a.x, a.y), fminf(a.z, a.w)));
        }
        cham += (double)m;
        emd  += (double)sqrtf(fmaxf(m, 0.0f));
    }
    // target-side col mins: min over 2 row-tiles; chamfer only.
    for (int i = tid; i < BATCH * NPTS; i += RBLOCKS * 256) {
        const float2 a = reinterpret_cast<const float2*>(g_colpart)[i];
        cham += (double)fminf(a.x, a.y);
    }
    for (int i = tid; i < BATCH * NPTS; i += RBLOCKS * 256)
        us += (double)unc[i];

    __shared__ double sc_[256], se_[256], su_[256];
    sc_[threadIdx.x] = cham; se_[threadIdx.x] = emd; su_[threadIdx.x] = us;
    __syncthreads();
    for (int s = 128; s > 0; s >>= 1) {
        if (threadIdx.x < s) {
            sc_[threadIdx.x] += sc_[threadIdx.x + s];
            se_[threadIdx.x] += se_[threadIdx.x + s];
            su_[threadIdx.x] += su_[threadIdx.x + s];
        }
        __syncthreads();
    }

    __shared__ int is_last;
    if (threadIdx.x == 0) {
        g_bsum[blockIdx.x][0] = sc_[0];
        g_bsum[blockIdx.x][1] = se_[0];
        g_bsum[blockIdx.x][2] = su_[0];
        __threadfence();
        unsigned int t = atomicAdd(&g_count, 1u);
        is_last = (t == RBLOCKS - 1);
    }
    __syncthreads();

    if (is_last) {
        __threadfence();
        double c = 0.0, e = 0.0, u = 0.0;
        if (threadIdx.x < RBLOCKS) {
            volatile double* p = &g_bsum[threadIdx.x][0];
            c = p[0]; e = p[1]; u = p[2];
        }
        sc_[threadIdx.x] = c; se_[threadIdx.x] = e; su_[threadIdx.x] = u;
        __syncthreads();
        for (int s = 32; s > 0; s >>= 1) {
            if (threadIdx.x < s) {
                sc_[threadIdx.x] += sc_[threadIdx.x + s];
                se_[threadIdx.x] += se_[threadIdx.x + s];
                su_[threadIdx.x] += su_[threadIdx.x + s];
            }
            __syncthreads();
        }
        if (threadIdx.x == 0) {
            const double inv = 1.0 / (double)(BATCH * NPTS);
            out[0] = (float)(sc_[0] * inv + 0.5 * (se_[0] * inv) + 0.01 * (su_[0] * inv));
            g_count = 0;   // reset for next graph replay
        }
    }
}

extern "C" void kernel_launch(void* const* d_in, const int* in_sizes, int n_in,
                              void* d_out, int out_size) {
    const float* pred = (const float*)d_in[0];   // [B, N, 3]
    const float* tgt  = (const float*)d_in[1];   // [B, M, 3]
    const float* unc  = (const float*)d_in[2];   // [B, N]
    float* out = (float*)d_out;                  // scalar

    dim3 grid(ROW_TILES, COL_TILES, BATCH);      // 2 x 16 x 8 = 256 blocks
    pair_min_kernel<<<grid, THREADS>>>(pred, tgt);
    reduce_kernel<<<RBLOCKS, 256>>>(unc, out);
}